// round 16
// baseline (speedup 1.0000x reference)
#include <cuda_runtime.h>
#include <cuda_bf16.h>
#include <cstdint>
#include <math.h>

#define NEG_INF_F   (-9.0e15f)

extern __shared__ char dyn_smem[];

// ============================================================================
// Helpers (battle-tested)
// ============================================================================
__device__ __forceinline__ uint32_t s2u(const void* p) {
    uint32_t a;
    asm("{ .reg .u64 t; cvta.to.shared.u64 t, %1; cvt.u32.u64 %0, t; }"
        : "=r"(a) : "l"(p));
    return a;
}
__device__ __forceinline__ void ldm_x4(uint32_t* r, uint32_t addr) {
    asm volatile("ldmatrix.sync.aligned.m8n8.x4.shared.b16 {%0,%1,%2,%3}, [%4];"
                 : "=r"(r[0]), "=r"(r[1]), "=r"(r[2]), "=r"(r[3]) : "r"(addr));
}
__device__ __forceinline__ void ldm_x4_trans(uint32_t* r, uint32_t addr) {
    asm volatile("ldmatrix.sync.aligned.m8n8.x4.trans.shared.b16 {%0,%1,%2,%3}, [%4];"
                 : "=r"(r[0]), "=r"(r[1]), "=r"(r[2]), "=r"(r[3]) : "r"(addr));
}
__device__ __forceinline__ void mma16816(float* c, const uint32_t* a, const uint32_t* b) {
    asm volatile(
        "mma.sync.aligned.m16n8k16.row.col.f32.bf16.bf16.f32 "
        "{%0,%1,%2,%3}, {%4,%5,%6,%7}, {%8,%9}, {%0,%1,%2,%3};"
        : "+f"(c[0]), "+f"(c[1]), "+f"(c[2]), "+f"(c[3])
        : "r"(a[0]), "r"(a[1]), "r"(a[2]), "r"(a[3]), "r"(b[0]), "r"(b[1]));
}
__device__ __forceinline__ uint32_t pack_bf2(float a, float b) {
    __nv_bfloat162 t = __floats2bfloat162_rn(a, b);
    return *(uint32_t*)&t;
}

// ============================================================================
// Device scratch: B^T in bf16 hi/lo, K padded to 1024 (zeros). Bt[n][k]=B[k][n]
// ============================================================================
__device__ __nv_bfloat16 g_Bh[128 * 1024];
__device__ __nv_bfloat16 g_Bl[128 * 1024];

__global__ void __launch_bounds__(256) bconv_kernel(const float* __restrict__ B) {
    int idx = blockIdx.x * 256 + threadIdx.x;   // 131072
    int n = idx & 127;
    int k = idx >> 7;
    float v = (k < 1000) ? B[k * 128 + n] : 0.f;
    __nv_bfloat16 h = __float2bfloat16(v);
    g_Bh[n * 1024 + k] = h;
    g_Bl[n * 1024 + k] = __float2bfloat16(v - __bfloat162float(h));
}

// ============================================================================
// Kernel B: attr GEMM, bf16 mma.sync split (C = AhBh + AlBh + AhBl)
// BM=32 so smem (46KB) co-resides with 2 attn CTAs (2x89KB) on one SM.
// grid=256, 8 warps = 2(M16) x 4(N32).
// ============================================================================
#define GK     1000
#define CH     64
#define NCH    16
#define PITCH  144
#define SA_H   0
#define SA_L   (32 * PITCH)                 // 4608
#define SB_H   (2 * 32 * PITCH)             // 9216
#define SB_L   (SB_H + 128 * PITCH)         // 27648
#define SMEM_GEMM (SB_L + 128 * PITCH)      // 46080

__global__ void __launch_bounds__(256)
attr_gemm_mma(const float* __restrict__ A, float* __restrict__ C) {
    char* smem = dyn_smem;
    const uint32_t sb = s2u(smem);
    const int tid  = threadIdx.x;
    const int wid  = tid >> 5;
    const int lane = tid & 31;
    const int bm   = blockIdx.x * 32;
    const int wm = wid >> 2;              // 0..1 (M 16-tile)
    const int wn = wid & 3;               // 0..3 (N 32-tile)

    const uint32_t aOff = (uint32_t)((lane & 15) * PITCH + (lane >> 4) * 16);
    const uint32_t bOff = (uint32_t)(((((lane >> 4) & 1) << 3) + (lane & 7)) * PITCH
                                     + ((lane >> 3) & 1) * 16);

    // staging: A rows (row = tid>>3, 8 k each), B rows (n = tid>>1, 32 k each)
    const int arow = tid >> 3, akseg = tid & 7;
    const int brow = tid >> 1, bseg  = tid & 1;
    const float* aptr = A + (size_t)(bm + arow) * GK;
    const __nv_bfloat16* bhp = g_Bh + brow * 1024 + bseg * 32;
    const __nv_bfloat16* blp = g_Bl + brow * 1024 + bseg * 32;

    float  as[8];
    uint4  bh4[4], bl4[4];

    {
        const float4* ap4 = (const float4*)(aptr + akseg * 8);
        float4 x = ap4[0], y = ap4[1];
        as[0]=x.x; as[1]=x.y; as[2]=x.z; as[3]=x.w;
        as[4]=y.x; as[5]=y.y; as[6]=y.z; as[7]=y.w;
        #pragma unroll
        for (int i = 0; i < 4; i++) {
            bh4[i] = *(const uint4*)(bhp + i * 8);
            bl4[i] = *(const uint4*)(blp + i * 8);
        }
    }

    float acc[4][4];
    #pragma unroll
    for (int nt = 0; nt < 4; nt++)
        #pragma unroll
        for (int q = 0; q < 4; q++) acc[nt][q] = 0.f;

    #pragma unroll 1
    for (int c = 0; c < NCH; c++) {
        if (c > 0) __syncthreads();

        {
            // A: 8 bf16 = 16 bytes per thread, hi + lo
            uint4 hv, lv;
            uint32_t* hw = (uint32_t*)&hv; uint32_t* lw = (uint32_t*)&lv;
            #pragma unroll
            for (int r = 0; r < 4; r++) {
                __nv_bfloat16 h0 = __float2bfloat16(as[2*r]);
                __nv_bfloat16 h1 = __float2bfloat16(as[2*r+1]);
                hw[r] = pack_bf2(as[2*r], as[2*r+1]);
                lw[r] = pack_bf2(as[2*r]   - __bfloat162float(h0),
                                 as[2*r+1] - __bfloat162float(h1));
            }
            *(uint4*)(smem + SA_H + arow * PITCH + akseg * 16) = hv;
            *(uint4*)(smem + SA_L + arow * PITCH + akseg * 16) = lv;

            char* pbh = smem + SB_H + brow * PITCH + bseg * 64;
            char* pbl = smem + SB_L + brow * PITCH + bseg * 64;
            #pragma unroll
            for (int i = 0; i < 4; i++) {
                *(uint4*)(pbh + i * 16) = bh4[i];
                *(uint4*)(pbl + i * 16) = bl4[i];
            }
        }
        __syncthreads();

        if (c + 1 < NCH) {
            const int k0 = (c + 1) * CH;
            if (c + 1 < NCH - 1) {
                const float4* ap4 = (const float4*)(aptr + k0 + akseg * 8);
                float4 x = ap4[0], y = ap4[1];
                as[0]=x.x; as[1]=x.y; as[2]=x.z; as[3]=x.w;
                as[4]=y.x; as[5]=y.y; as[6]=y.z; as[7]=y.w;
            } else {                      // tail chunk guard (K=1000)
                #pragma unroll
                for (int i = 0; i < 8; i++) {
                    int kg = k0 + akseg * 8 + i;
                    as[i] = (kg < GK) ? aptr[kg] : 0.f;
                }
            }
            #pragma unroll
            for (int i = 0; i < 4; i++) {
                bh4[i] = *(const uint4*)(bhp + k0 + i * 8);
                bl4[i] = *(const uint4*)(blp + k0 + i * 8);
            }
        }

        const uint32_t aBaseH = sb + SA_H + (uint32_t)(wm * 16 * PITCH) + aOff;
        const uint32_t aBaseL = sb + SA_L + (uint32_t)(wm * 16 * PITCH) + aOff;
        const uint32_t bBaseH = sb + SB_H + (uint32_t)(wn * 32 * PITCH) + bOff;
        const uint32_t bBaseL = sb + SB_L + (uint32_t)(wn * 32 * PITCH) + bOff;

        #pragma unroll
        for (int ks = 0; ks < 4; ks++) {
            uint32_t ah[4], al[4], bhv[2][4], blv[2][4];
            ldm_x4(ah, aBaseH + ks * 32);
            ldm_x4(al, aBaseL + ks * 32);
            #pragma unroll
            for (int nh = 0; nh < 2; nh++) {
                ldm_x4(bhv[nh], bBaseH + nh * 16 * PITCH + ks * 32);
                ldm_x4(blv[nh], bBaseL + nh * 16 * PITCH + ks * 32);
            }
            #pragma unroll
            for (int nt = 0; nt < 4; nt++) {
                const uint32_t* bhreg = &bhv[nt >> 1][(nt & 1) * 2];
                const uint32_t* blreg = &blv[nt >> 1][(nt & 1) * 2];
                mma16816(acc[nt], ah, bhreg);
                mma16816(acc[nt], al, bhreg);
                mma16816(acc[nt], ah, blreg);
            }
        }
    }

    const int g = lane >> 2, t = lane & 3;
    #pragma unroll
    for (int nt = 0; nt < 4; nt++) {
        int row0 = bm + wm * 16 + g;
        int col  = wn * 32 + nt * 8 + t * 2;
        *(float2*)&C[(size_t)row0 * 128 + col] =
            make_float2(acc[nt][0], acc[nt][1]);
        *(float2*)&C[(size_t)(row0 + 8) * 128 + col] =
            make_float2(acc[nt][2], acc[nt][3]);
    }
}

// ============================================================================
// Kernel A: tensor-core attention v2 (unchanged from R15 — proven, 34.5us)
// ============================================================================
#define PB      272
#define HB_H    0
#define HB_L    34816
#define AK_H    69632
#define AK_L    78336
#define ATT_H   69632
#define ATT_L   78336
#define RMAX_W  (87040 / 4)
#define RSUM_W  (87552 / 4)
#define A_SW    (88064 / 4)
#define SGN_W   (90112 / 4)
#define SMEM_ATTN_TC 91136

__global__ void __launch_bounds__(256, 2)
attn_tc_kernel(const float* __restrict__ hidden,
               const int*   __restrict__ adj,
               const float* __restrict__ a,
               float*       __restrict__ out)
{
    char*     smem  = dyn_smem;
    float*    smemf = (float*)dyn_smem;
    float*    rmax  = smemf + RMAX_W;
    float*    rsum  = smemf + RSUM_W;
    float*    a_s   = smemf + A_SW;
    uint32_t* sgn_s = (uint32_t*)dyn_smem + SGN_W;
    const uint32_t sb = s2u(smem);

    const int tid  = threadIdx.x;
    const int wid  = tid >> 5;
    const int lane = tid & 31;
    const int b    = blockIdx.x;
    const int ibase = b * 128 + blockIdx.y * 32;

    const int wm = wid >> 2, wn = wid & 3;
    const int g = lane >> 2, t = lane & 3;
    const uint32_t aOff  = (uint32_t)((lane & 15) * PB + (lane >> 4) * 16);
    const uint32_t bOff  = (uint32_t)(((((lane >> 4) & 1) << 3) + (lane & 7)) * PB
                                      + ((lane >> 3) & 1) * 16);
    const uint32_t bOffT = (uint32_t)(((lane & 7) + ((lane >> 3) & 1) * 8) * PB
                                      + ((lane >> 4) & 1) * 16);

    for (int q = tid; q < 2048; q += 256) {
        int j = q >> 4, db = (q & 15) * 8;
        const float* hp = hidden + (size_t)(b * 128 + j) * 128 + db;
        float4 x = *(const float4*)hp, y = *(const float4*)(hp + 4);
        float f[8] = {x.x, x.y, x.z, x.w, y.x, y.y, y.z, y.w};
        uint4 hv, lv;
        uint32_t* hw = (uint32_t*)&hv; uint32_t* lw = (uint32_t*)&lv;
        #pragma unroll
        for (int r = 0; r < 4; r++) {
            __nv_bfloat16 h0 = __float2bfloat16(f[2*r]);
            __nv_bfloat16 h1 = __float2bfloat16(f[2*r+1]);
            hw[r] = pack_bf2(f[2*r], f[2*r+1]);
            lw[r] = pack_bf2(f[2*r]   - __bfloat162float(h0),
                             f[2*r+1] - __bfloat162float(h1));
        }
        *(uint4*)(smem + HB_H + j * PB + db * 2) = hv;
        *(uint4*)(smem + HB_L + j * PB + db * 2) = lv;
    }
    for (int q = tid; q < 512; q += 256) a_s[q] = a[q];
    {
        int kk = tid >> 6, ks = (tid >> 3) & 7, tt = (tid >> 1) & 3, hf = tid & 1;
        int d0 = ks * 16 + 2 * tt + hf * 8;
        uint32_t m = (a[d0 * 4 + kk] < 0.f ? 0x8000u : 0u)
                   | (a[(d0 + 1) * 4 + kk] < 0.f ? 0x80000000u : 0u);
        sgn_s[tid] = m;
    }

    uint32_t km0 = 0, km1 = 0, km2 = 0, km3 = 0;
    #pragma unroll
    for (int nt = 0; nt < 4; nt++)
        #pragma unroll
        for (int q = 0; q < 4; q++) {
            int il = wm * 16 + g + (q >> 1) * 8;
            int j  = wn * 32 + nt * 8 + 2 * t + (q & 1);
            int av = adj[(size_t)(ibase + il) * 128 + j];
            int p  = nt * 4 + q;
            km0 |= (uint32_t)(av == 1) << p;
            km1 |= (uint32_t)(av == 2) << p;
            km2 |= (uint32_t)(av == 3) << p;
            km3 |= (uint32_t)(av == 4) << p;
        }

    float alpha[4][4];
    #pragma unroll
    for (int nt = 0; nt < 4; nt++)
        #pragma unroll
        for (int q = 0; q < 4; q++) alpha[nt][q] = NEG_INF_F;

    const int arow = tid >> 3, dseg = (tid & 7) * 16;

    #pragma unroll 1
    for (int k = 0; k < 4; k++) {
        __syncthreads();

        {
            const float* hrow = hidden + (size_t)(ibase + arow) * 128 + dseg;
            #pragma unroll
            for (int gq = 0; gq < 2; gq++) {
                float4 x = *(const float4*)(hrow + gq * 8);
                float4 y = *(const float4*)(hrow + gq * 8 + 4);
                float f[8] = {x.x, x.y, x.z, x.w, y.x, y.y, y.z, y.w};
                uint4 hv, lv;
                uint32_t* hw = (uint32_t*)&hv; uint32_t* lw = (uint32_t*)&lv;
                #pragma unroll
                for (int r = 0; r < 4; r++) {
                    int d0 = dseg + gq * 8 + 2 * r;
                    float f0 = f[2*r]     * a_s[d0 * 4 + k];
                    float f1 = f[2*r + 1] * a_s[(d0 + 1) * 4 + k];
                    __nv_bfloat16 h0 = __float2bfloat16(f0);
                    __nv_bfloat16 h1 = __float2bfloat16(f1);
                    hw[r] = pack_bf2(f0, f1);
                    lw[r] = pack_bf2(f0 - __bfloat162float(h0),
                                     f1 - __bfloat162float(h1));
                }
                *(uint4*)(smem + AK_H + arow * PB + (dseg + gq * 8) * 2) = hv;
                *(uint4*)(smem + AK_L + arow * PB + (dseg + gq * 8) * 2) = lv;
            }
        }
        __syncthreads();

        float Sid[4][4], Sab[4][4];
        #pragma unroll
        for (int nt = 0; nt < 4; nt++)
            #pragma unroll
            for (int q = 0; q < 4; q++) { Sid[nt][q] = 0.f; Sab[nt][q] = 0.f; }

        const uint32_t akh = sb + AK_H + (uint32_t)(wm * 16 * PB) + aOff;
        const uint32_t akl = sb + AK_L + (uint32_t)(wm * 16 * PB) + aOff;
        const uint32_t hbh = sb + HB_H + (uint32_t)(wn * 32 * PB) + bOff;
        const uint32_t hbl = sb + HB_L + (uint32_t)(wn * 32 * PB) + bOff;

        #pragma unroll
        for (int ks = 0; ks < 8; ks++) {
            uint32_t ah[4], al[4], bh[2][4], bl[2][4];
            ldm_x4(ah, akh + ks * 32);
            ldm_x4(al, akl + ks * 32);
            #pragma unroll
            for (int nh = 0; nh < 2; nh++) {
                ldm_x4(bh[nh], hbh + nh * 16 * PB + ks * 32);
                ldm_x4(bl[nh], hbl + nh * 16 * PB + ks * 32);
            }

            #pragma unroll
            for (int nt = 0; nt < 4; nt++) {
                const uint32_t* bhr = &bh[nt >> 1][(nt & 1) * 2];
                const uint32_t* blr = &bl[nt >> 1][(nt & 1) * 2];
                mma16816(Sid[nt], ah, bhr);
                mma16816(Sid[nt], al, bhr);
                mma16816(Sid[nt], ah, blr);
            }

            uint32_t m01 = sgn_s[((k * 8 + ks) * 4 + t) * 2];
            uint32_t m23 = sgn_s[((k * 8 + ks) * 4 + t) * 2 + 1];
            #pragma unroll
            for (int r = 0; r < 4; r++) {
                uint32_t mm = (r < 2) ? m01 : m23;
                al[r] = al[r] ^ (ah[r] & 0x80008000u) ^ mm;
                ah[r] = (ah[r] & 0x7FFF7FFFu) ^ mm;
            }
            #pragma unroll
            for (int nh = 0; nh < 2; nh++)
                #pragma unroll
                for (int r = 0; r < 4; r++) {
                    bl[nh][r] = bl[nh][r] ^ (bh[nh][r] & 0x80008000u);
                    bh[nh][r] = bh[nh][r] & 0x7FFF7FFFu;
                }

            #pragma unroll
            for (int nt = 0; nt < 4; nt++) {
                const uint32_t* bhr = &bh[nt >> 1][(nt & 1) * 2];
                const uint32_t* blr = &bl[nt >> 1][(nt & 1) * 2];
                mma16816(Sab[nt], ah, bhr);
                mma16816(Sab[nt], al, bhr);
                mma16816(Sab[nt], ah, blr);
            }
        }

        uint32_t mk = (k == 0) ? km0 : (k == 1) ? km1 : (k == 2) ? km2 : km3;
        #pragma unroll
        for (int nt = 0; nt < 4; nt++)
            #pragma unroll
            for (int q = 0; q < 4; q++) {
                float combo = fmaf(0.6f, Sid[nt][q], 0.4f * Sab[nt][q]);
                int p = nt * 4 + q;
                if ((mk >> p) & 1u) alpha[nt][q] = combo;
            }
    }

    // ---- softmax in registers ----
    float mloc[2];
    #pragma unroll
    for (int qh = 0; qh < 2; qh++) {
        float m = NEG_INF_F;
        #pragma unroll
        for (int nt = 0; nt < 4; nt++) {
            m = fmaxf(m, alpha[nt][qh * 2 + 0]);
            m = fmaxf(m, alpha[nt][qh * 2 + 1]);
        }
        m = fmaxf(m, __shfl_xor_sync(0xffffffffu, m, 1));
        m = fmaxf(m, __shfl_xor_sync(0xffffffffu, m, 2));
        mloc[qh] = m;
    }
    if (t == 0) {
        rmax[(wm * 16 + 0 * 8 + g) * 4 + wn] = mloc[0];
        rmax[(wm * 16 + 1 * 8 + g) * 4 + wn] = mloc[1];
    }
    __syncthreads();

    float inv[2];
    #pragma unroll
    for (int qh = 0; qh < 2; qh++) {
        int row = wm * 16 + qh * 8 + g;
        float m = fmaxf(fmaxf(rmax[row * 4 + 0], rmax[row * 4 + 1]),
                        fmaxf(rmax[row * 4 + 2], rmax[row * 4 + 3]));
        float s = 0.f;
        #pragma unroll
        for (int nt = 0; nt < 4; nt++) {
            alpha[nt][qh * 2 + 0] = __expf(alpha[nt][qh * 2 + 0] - m);
            alpha[nt][qh * 2 + 1] = __expf(alpha[nt][qh * 2 + 1] - m);
            s += alpha[nt][qh * 2 + 0] + alpha[nt][qh * 2 + 1];
        }
        s += __shfl_xor_sync(0xffffffffu, s, 1);
        s += __shfl_xor_sync(0xffffffffu, s, 2);
        if (t == 0) rsum[row * 4 + wn] = s;
    }
    __syncthreads();
    #pragma unroll
    for (int qh = 0; qh < 2; qh++) {
        int row = wm * 16 + qh * 8 + g;
        float s = (rsum[row * 4 + 0] + rsum[row * 4 + 1]) +
                  (rsum[row * 4 + 2] + rsum[row * 4 + 3]);
        inv[qh] = 1.f / s;
    }

    // ---- write attn probs as bf16 hi/lo ATT tiles (overlay AK) ----
    #pragma unroll
    for (int qh = 0; qh < 2; qh++) {
        int row = wm * 16 + qh * 8 + g;
        #pragma unroll
        for (int nt = 0; nt < 4; nt++) {
            float p0 = alpha[nt][qh * 2 + 0] * inv[qh];
            float p1 = alpha[nt][qh * 2 + 1] * inv[qh];
            __nv_bfloat16 h0 = __float2bfloat16(p0);
            __nv_bfloat16 h1 = __float2bfloat16(p1);
            uint32_t hw = pack_bf2(p0, p1);
            uint32_t lw = pack_bf2(p0 - __bfloat162float(h0),
                                   p1 - __bfloat162float(h1));
            uint32_t off = (uint32_t)(row * PB + (wn * 32 + nt * 8 + 2 * t) * 2);
            *(uint32_t*)(smem + ATT_H + off) = hw;
            *(uint32_t*)(smem + ATT_L + off) = lw;
        }
    }
    __syncthreads();

    // ---- AV GEMM: out = attn @ H; B-frags via trans ldmatrix from HB ----
    float O[4][4];
    #pragma unroll
    for (int nt = 0; nt < 4; nt++)
        #pragma unroll
        for (int q = 0; q < 4; q++) O[nt][q] = 0.f;

    const uint32_t ath = sb + ATT_H + (uint32_t)(wm * 16 * PB) + aOff;
    const uint32_t atl = sb + ATT_L + (uint32_t)(wm * 16 * PB) + aOff;

    #pragma unroll
    for (int ks = 0; ks < 8; ks++) {
        uint32_t ah[4], al[4], bh[2][4], bl[2][4];
        ldm_x4(ah, ath + ks * 32);
        ldm_x4(al, atl + ks * 32);
        #pragma unroll
        for (int nh = 0; nh < 2; nh++) {
            uint32_t base = (uint32_t)(ks * 16 * PB + (wn * 32 + nh * 16) * 2) + bOffT;
            ldm_x4_trans(bh[nh], sb + HB_H + base);
            ldm_x4_trans(bl[nh], sb + HB_L + base);
        }
        #pragma unroll
        for (int nt = 0; nt < 4; nt++) {
            const uint32_t* bhr = &bh[nt >> 1][(nt & 1) * 2];
            const uint32_t* blr = &bl[nt >> 1][(nt & 1) * 2];
            mma16816(O[nt], ah, bhr);
            mma16816(O[nt], al, bhr);
            mma16816(O[nt], ah, blr);
        }
    }

    #pragma unroll
    for (int nt = 0; nt < 4; nt++) {
        int row0 = ibase + wm * 16 + g;
        int col  = wn * 32 + nt * 8 + t * 2;
        *(float2*)&out[(size_t)row0 * 128 + col] =
            make_float2(O[nt][0], O[nt][1]);
        *(float2*)&out[(size_t)(row0 + 8) * 128 + col] =
            make_float2(O[nt][2], O[nt][3]);
    }
}

// ============================================================================
// Launch: fork/join — attn_tc overlaps bconv -> attr_gemm (now co-resident).
// ============================================================================
extern "C" void kernel_launch(void* const* d_in, const int* in_sizes, int n_in,
                              void* d_out, int out_size)
{
    const float* hidden   = (const float*)d_in[0];  // [64,128,128]
    const int*   adj      = (const int*)  d_in[1];  // [64,128,128]
    const float* a        = (const float*)d_in[2];  // [128,4]
    const float* A_attr   = (const float*)d_in[3];  // [64,128,1000]
    const float* attr_emb = (const float*)d_in[4];  // [1000,128]

    float* out       = (float*)d_out;
    float* out_attn  = out;                   // output    [64,128,128]
    float* out_attr  = out + 64 * 128 * 128;  // attr_sess [64,128,128]

    static cudaStream_t s_side = nullptr;
    static cudaEvent_t  ev_fork = nullptr, ev_join = nullptr;
    if (s_side == nullptr) {
        cudaStreamCreateWithFlags(&s_side, cudaStreamNonBlocking);
        cudaEventCreateWithFlags(&ev_fork, cudaEventDisableTiming);
        cudaEventCreateWithFlags(&ev_join, cudaEventDisableTiming);
        cudaFuncSetAttribute(attn_tc_kernel,
                             cudaFuncAttributeMaxDynamicSharedMemorySize,
                             SMEM_ATTN_TC);
        cudaFuncSetAttribute(attr_gemm_mma,
                             cudaFuncAttributeMaxDynamicSharedMemorySize,
                             SMEM_GEMM);
    }

    cudaEventRecord(ev_fork, 0);
    cudaStreamWaitEvent(s_side, ev_fork, 0);

    attn_tc_kernel<<<dim3(64, 4), 256, SMEM_ATTN_TC, s_side>>>(
        hidden, adj, a, out_attn);
    cudaEventRecord(ev_join, s_side);

    bconv_kernel<<<512, 256>>>(attr_emb);
    attr_gemm_mma<<<256, 256, SMEM_GEMM>>>(A_attr, out_attr);

    cudaStreamWaitEvent(0, ev_join, 0);
}

// round 17
// speedup vs baseline: 1.0571x; 1.0571x over previous
#include <cuda_runtime.h>
#include <cuda_bf16.h>
#include <cstdint>
#include <math.h>

#define NEG_INF_F   (-9.0e15f)

extern __shared__ char dyn_smem[];

// ============================================================================
// Helpers (battle-tested)
// ============================================================================
__device__ __forceinline__ uint32_t s2u(const void* p) {
    uint32_t a;
    asm("{ .reg .u64 t; cvta.to.shared.u64 t, %1; cvt.u32.u64 %0, t; }"
        : "=r"(a) : "l"(p));
    return a;
}
__device__ __forceinline__ void ldm_x4(uint32_t* r, uint32_t addr) {
    asm volatile("ldmatrix.sync.aligned.m8n8.x4.shared.b16 {%0,%1,%2,%3}, [%4];"
                 : "=r"(r[0]), "=r"(r[1]), "=r"(r[2]), "=r"(r[3]) : "r"(addr));
}
__device__ __forceinline__ void ldm_x4_trans(uint32_t* r, uint32_t addr) {
    asm volatile("ldmatrix.sync.aligned.m8n8.x4.trans.shared.b16 {%0,%1,%2,%3}, [%4];"
                 : "=r"(r[0]), "=r"(r[1]), "=r"(r[2]), "=r"(r[3]) : "r"(addr));
}
__device__ __forceinline__ void mma16816(float* c, const uint32_t* a, const uint32_t* b) {
    asm volatile(
        "mma.sync.aligned.m16n8k16.row.col.f32.bf16.bf16.f32 "
        "{%0,%1,%2,%3}, {%4,%5,%6,%7}, {%8,%9}, {%0,%1,%2,%3};"
        : "+f"(c[0]), "+f"(c[1]), "+f"(c[2]), "+f"(c[3])
        : "r"(a[0]), "r"(a[1]), "r"(a[2]), "r"(a[3]), "r"(b[0]), "r"(b[1]));
}
__device__ __forceinline__ uint32_t pack_bf2(float a, float b) {
    __nv_bfloat162 t = __floats2bfloat162_rn(a, b);
    return *(uint32_t*)&t;
}

// ============================================================================
// Device scratch: B^T in bf16 hi/lo, K padded to 1024 (zeros). Bt[n][k]=B[k][n]
// ============================================================================
__device__ __nv_bfloat16 g_Bh[128 * 1024];
__device__ __nv_bfloat16 g_Bl[128 * 1024];

// bconv v2: smem transpose -> coalesced reads AND 64B vector writes.
__global__ void __launch_bounds__(256) bconv_kernel(const float* __restrict__ B) {
    __shared__ float tile[64 * 128];
    const int k0 = blockIdx.x * 64;      // grid = 16
    for (int q = threadIdx.x; q < 8192; q += 256) {
        int kk = q >> 7, n = q & 127;
        int k = k0 + kk;
        tile[q] = (k < 1000) ? B[k * 128 + n] : 0.f;
    }
    __syncthreads();
    const int n    = threadIdx.x >> 1;
    const int kk0  = (threadIdx.x & 1) * 32;
    uint32_t hw[16], lw[16];
    #pragma unroll
    for (int i = 0; i < 16; i++) {
        float f0 = tile[(kk0 + 2 * i)     * 128 + n];
        float f1 = tile[(kk0 + 2 * i + 1) * 128 + n];
        __nv_bfloat16 h0 = __float2bfloat16(f0), h1 = __float2bfloat16(f1);
        hw[i] = pack_bf2(f0, f1);
        lw[i] = pack_bf2(f0 - __bfloat162float(h0), f1 - __bfloat162float(h1));
    }
    uint4* dh = (uint4*)(g_Bh + n * 1024 + k0 + kk0);
    uint4* dl = (uint4*)(g_Bl + n * 1024 + k0 + kk0);
    #pragma unroll
    for (int i = 0; i < 4; i++) {
        dh[i] = make_uint4(hw[4*i], hw[4*i+1], hw[4*i+2], hw[4*i+3]);
        dl[i] = make_uint4(lw[4*i], lw[4*i+1], lw[4*i+2], lw[4*i+3]);
    }
}

// ============================================================================
// Kernel B: attr GEMM, bf16 mma.sync split — R15 BM=64 config (proven fast).
// ============================================================================
#define GK     1000
#define CH     64
#define NCH    16
#define PITCH  144
#define SA_H   0
#define SA_L   (64 * PITCH)
#define SB_H   (2 * 64 * PITCH)
#define SB_L   (SB_H + 128 * PITCH)
#define SMEM_GEMM (SB_L + 128 * PITCH)      // 55296

__global__ void __launch_bounds__(256)
attr_gemm_mma(const float* __restrict__ A, float* __restrict__ C) {
    char* smem = dyn_smem;
    const uint32_t sb = s2u(smem);
    const int tid  = threadIdx.x;
    const int wid  = tid >> 5;
    const int lane = tid & 31;
    const int bm   = blockIdx.x * 64;
    const int wm = wid >> 2;
    const int wn = wid & 3;

    const uint32_t aOff = (uint32_t)((lane & 15) * PITCH + (lane >> 4) * 16);
    const uint32_t bOff = (uint32_t)(((((lane >> 4) & 1) << 3) + (lane & 7)) * PITCH
                                     + ((lane >> 3) & 1) * 16);

    const int arow = tid >> 2, akseg = tid & 3;
    const int brow = tid >> 1, bseg  = tid & 1;
    const float* aptr = A + (size_t)(bm + arow) * GK;
    const __nv_bfloat16* bhp = g_Bh + brow * 1024 + bseg * 32;
    const __nv_bfloat16* blp = g_Bl + brow * 1024 + bseg * 32;

    float  as[16];
    uint4  bh4[4], bl4[4];

    {
        const float4* ap4 = (const float4*)(aptr + akseg * 16);
        #pragma unroll
        for (int i = 0; i < 4; i++) {
            float4 v = ap4[i];
            as[4*i+0] = v.x; as[4*i+1] = v.y; as[4*i+2] = v.z; as[4*i+3] = v.w;
        }
        #pragma unroll
        for (int i = 0; i < 4; i++) {
            bh4[i] = *(const uint4*)(bhp + i * 8);
            bl4[i] = *(const uint4*)(blp + i * 8);
        }
    }

    float acc[2][4][4];
    #pragma unroll
    for (int mt = 0; mt < 2; mt++)
        #pragma unroll
        for (int nt = 0; nt < 4; nt++)
            #pragma unroll
            for (int q = 0; q < 4; q++) acc[mt][nt][q] = 0.f;

    #pragma unroll 1
    for (int c = 0; c < NCH; c++) {
        if (c > 0) __syncthreads();

        {
            char* pa = smem + SA_H + arow * PITCH + akseg * 32;
            char* pl = smem + SA_L + arow * PITCH + akseg * 32;
            uint4 hv, lv;
            #pragma unroll
            for (int half = 0; half < 2; half++) {
                const float* f = as + half * 8;
                __nv_bfloat16 h0 = __float2bfloat16(f[0]), h1 = __float2bfloat16(f[1]);
                __nv_bfloat16 h2 = __float2bfloat16(f[2]), h3 = __float2bfloat16(f[3]);
                __nv_bfloat16 h4 = __float2bfloat16(f[4]), h5 = __float2bfloat16(f[5]);
                __nv_bfloat16 h6 = __float2bfloat16(f[6]), h7 = __float2bfloat16(f[7]);
                hv.x = pack_bf2(f[0], f[1]); hv.y = pack_bf2(f[2], f[3]);
                hv.z = pack_bf2(f[4], f[5]); hv.w = pack_bf2(f[6], f[7]);
                lv.x = pack_bf2(f[0]-__bfloat162float(h0), f[1]-__bfloat162float(h1));
                lv.y = pack_bf2(f[2]-__bfloat162float(h2), f[3]-__bfloat162float(h3));
                lv.z = pack_bf2(f[4]-__bfloat162float(h4), f[5]-__bfloat162float(h5));
                lv.w = pack_bf2(f[6]-__bfloat162float(h6), f[7]-__bfloat162float(h7));
                *(uint4*)(pa + half * 16) = hv;
                *(uint4*)(pl + half * 16) = lv;
            }
            char* pbh = smem + SB_H + brow * PITCH + bseg * 64;
            char* pbl = smem + SB_L + brow * PITCH + bseg * 64;
            #pragma unroll
            for (int i = 0; i < 4; i++) {
                *(uint4*)(pbh + i * 16) = bh4[i];
                *(uint4*)(pbl + i * 16) = bl4[i];
            }
        }
        __syncthreads();

        if (c + 1 < NCH) {
            const int k0 = (c + 1) * CH;
            if (c + 1 < NCH - 1) {
                const float4* ap4 = (const float4*)(aptr + k0 + akseg * 16);
                #pragma unroll
                for (int i = 0; i < 4; i++) {
                    float4 v = ap4[i];
                    as[4*i+0]=v.x; as[4*i+1]=v.y; as[4*i+2]=v.z; as[4*i+3]=v.w;
                }
            } else {
                #pragma unroll
                for (int i = 0; i < 16; i++) {
                    int kg = k0 + akseg * 16 + i;
                    as[i] = (kg < GK) ? aptr[kg] : 0.f;
                }
            }
            #pragma unroll
            for (int i = 0; i < 4; i++) {
                bh4[i] = *(const uint4*)(bhp + k0 + i * 8);
                bl4[i] = *(const uint4*)(blp + k0 + i * 8);
            }
        }

        const uint32_t aBaseH = sb + SA_H + (uint32_t)(wm * 32 * PITCH) + aOff;
        const uint32_t aBaseL = sb + SA_L + (uint32_t)(wm * 32 * PITCH) + aOff;
        const uint32_t bBaseH = sb + SB_H + (uint32_t)(wn * 32 * PITCH) + bOff;
        const uint32_t bBaseL = sb + SB_L + (uint32_t)(wn * 32 * PITCH) + bOff;

        #pragma unroll
        for (int ks = 0; ks < 4; ks++) {
            uint32_t ah[2][4], al[2][4], bhv[2][4], blv[2][4];
            #pragma unroll
            for (int mt = 0; mt < 2; mt++) {
                ldm_x4(ah[mt], aBaseH + mt * 16 * PITCH + ks * 32);
                ldm_x4(al[mt], aBaseL + mt * 16 * PITCH + ks * 32);
            }
            #pragma unroll
            for (int nh = 0; nh < 2; nh++) {
                ldm_x4(bhv[nh], bBaseH + nh * 16 * PITCH + ks * 32);
                ldm_x4(blv[nh], bBaseL + nh * 16 * PITCH + ks * 32);
            }
            #pragma unroll
            for (int mt = 0; mt < 2; mt++)
                #pragma unroll
                for (int nt = 0; nt < 4; nt++) {
                    const uint32_t* bhreg = &bhv[nt >> 1][(nt & 1) * 2];
                    const uint32_t* blreg = &blv[nt >> 1][(nt & 1) * 2];
                    mma16816(acc[mt][nt], ah[mt], bhreg);
                    mma16816(acc[mt][nt], al[mt], bhreg);
                    mma16816(acc[mt][nt], ah[mt], blreg);
                }
        }
    }

    const int g = lane >> 2, t = lane & 3;
    #pragma unroll
    for (int mt = 0; mt < 2; mt++)
        #pragma unroll
        for (int nt = 0; nt < 4; nt++) {
            int row0 = bm + wm * 32 + mt * 16 + g;
            int col  = wn * 32 + nt * 8 + t * 2;
            *(float2*)&C[(size_t)row0 * 128 + col] =
                make_float2(acc[mt][nt][0], acc[mt][nt][1]);
            *(float2*)&C[(size_t)(row0 + 8) * 128 + col] =
                make_float2(acc[mt][nt][2], acc[mt][nt][3]);
        }
}

// ============================================================================
// Kernel A: tensor-core attention v3 — AK double-buffered (1 sync per k,
// staging overlaps MMA). Otherwise identical to proven R15 v2.
// ============================================================================
#define PB      272
#define HB_H    0
#define HB_L    34816
#define AK0_H   69632
#define AK0_L   78336
#define AK1_H   87040
#define AK1_L   95744
#define ATT_H   69632                        // overlays AK0
#define ATT_L   78336
#define RMAX_W  (104448 / 4)
#define RSUM_W  (104960 / 4)
#define A_SW    (105472 / 4)
#define SGN_W   (107520 / 4)
#define SMEM_ATTN_TC 108544

__global__ void __launch_bounds__(256, 2)
attn_tc_kernel(const float* __restrict__ hidden,
               const int*   __restrict__ adj,
               const float* __restrict__ a,
               float*       __restrict__ out)
{
    char*     smem  = dyn_smem;
    float*    smemf = (float*)dyn_smem;
    float*    rmax  = smemf + RMAX_W;
    float*    rsum  = smemf + RSUM_W;
    float*    a_s   = smemf + A_SW;
    uint32_t* sgn_s = (uint32_t*)dyn_smem + SGN_W;
    const uint32_t sb = s2u(smem);

    const int tid  = threadIdx.x;
    const int wid  = tid >> 5;
    const int lane = tid & 31;
    const int b    = blockIdx.x;
    const int ibase = b * 128 + blockIdx.y * 32;

    const int wm = wid >> 2, wn = wid & 3;
    const int g = lane >> 2, t = lane & 3;
    const uint32_t aOff  = (uint32_t)((lane & 15) * PB + (lane >> 4) * 16);
    const uint32_t bOff  = (uint32_t)(((((lane >> 4) & 1) << 3) + (lane & 7)) * PB
                                      + ((lane >> 3) & 1) * 16);
    const uint32_t bOffT = (uint32_t)(((lane & 7) + ((lane >> 3) & 1) * 8) * PB
                                      + ((lane >> 4) & 1) * 16);

    // ---- stage full H -> HB hi/lo ----
    for (int q = tid; q < 2048; q += 256) {
        int j = q >> 4, db = (q & 15) * 8;
        const float* hp = hidden + (size_t)(b * 128 + j) * 128 + db;
        float4 x = *(const float4*)hp, y = *(const float4*)(hp + 4);
        float f[8] = {x.x, x.y, x.z, x.w, y.x, y.y, y.z, y.w};
        uint4 hv, lv;
        uint32_t* hw = (uint32_t*)&hv; uint32_t* lw = (uint32_t*)&lv;
        #pragma unroll
        for (int r = 0; r < 4; r++) {
            __nv_bfloat16 h0 = __float2bfloat16(f[2*r]);
            __nv_bfloat16 h1 = __float2bfloat16(f[2*r+1]);
            hw[r] = pack_bf2(f[2*r], f[2*r+1]);
            lw[r] = pack_bf2(f[2*r]   - __bfloat162float(h0),
                             f[2*r+1] - __bfloat162float(h1));
        }
        *(uint4*)(smem + HB_H + j * PB + db * 2) = hv;
        *(uint4*)(smem + HB_L + j * PB + db * 2) = lv;
    }
    for (int q = tid; q < 512; q += 256) a_s[q] = a[q];
    {
        int kk = tid >> 6, ks = (tid >> 3) & 7, tt = (tid >> 1) & 3, hf = tid & 1;
        int d0 = ks * 16 + 2 * tt + hf * 8;
        uint32_t m = (a[d0 * 4 + kk] < 0.f ? 0x8000u : 0u)
                   | (a[(d0 + 1) * 4 + kk] < 0.f ? 0x80000000u : 0u);
        sgn_s[tid] = m;
    }

    uint32_t km0 = 0, km1 = 0, km2 = 0, km3 = 0;
    #pragma unroll
    for (int nt = 0; nt < 4; nt++)
        #pragma unroll
        for (int q = 0; q < 4; q++) {
            int il = wm * 16 + g + (q >> 1) * 8;
            int j  = wn * 32 + nt * 8 + 2 * t + (q & 1);
            int av = adj[(size_t)(ibase + il) * 128 + j];
            int p  = nt * 4 + q;
            km0 |= (uint32_t)(av == 1) << p;
            km1 |= (uint32_t)(av == 2) << p;
            km2 |= (uint32_t)(av == 3) << p;
            km3 |= (uint32_t)(av == 4) << p;
        }

    float alpha[4][4];
    #pragma unroll
    for (int nt = 0; nt < 4; nt++)
        #pragma unroll
        for (int q = 0; q < 4; q++) alpha[nt][q] = NEG_INF_F;

    const int arow = tid >> 3, dseg = (tid & 7) * 16;
    const float* hrow = hidden + (size_t)(ibase + arow) * 128 + dseg;

    // stage A_k for edge type kk into smem offsets (oh, ol)
    auto stage_ak = [&](int kk, int oh, int ol) {
        #pragma unroll
        for (int gq = 0; gq < 2; gq++) {
            float4 x = *(const float4*)(hrow + gq * 8);
            float4 y = *(const float4*)(hrow + gq * 8 + 4);
            float f[8] = {x.x, x.y, x.z, x.w, y.x, y.y, y.z, y.w};
            uint4 hv, lv;
            uint32_t* hw = (uint32_t*)&hv; uint32_t* lw = (uint32_t*)&lv;
            #pragma unroll
            for (int r = 0; r < 4; r++) {
                int d0 = dseg + gq * 8 + 2 * r;
                float f0 = f[2*r]     * a_s[d0 * 4 + kk];
                float f1 = f[2*r + 1] * a_s[(d0 + 1) * 4 + kk];
                __nv_bfloat16 h0 = __float2bfloat16(f0);
                __nv_bfloat16 h1 = __float2bfloat16(f1);
                hw[r] = pack_bf2(f0, f1);
                lw[r] = pack_bf2(f0 - __bfloat162float(h0),
                                 f1 - __bfloat162float(h1));
            }
            *(uint4*)(smem + oh + arow * PB + (dseg + gq * 8) * 2) = hv;
            *(uint4*)(smem + ol + arow * PB + (dseg + gq * 8) * 2) = lv;
        }
    };

    __syncthreads();              // HB/a_s staging visible
    stage_ak(0, AK0_H, AK0_L);
    __syncthreads();

    // ==================== k-loop, double-buffered AK ====================
    #pragma unroll 1
    for (int k = 0; k < 4; k++) {
        const int cur = k & 1;
        const uint32_t akh = sb + (cur ? AK1_H : AK0_H) + (uint32_t)(wm * 16 * PB) + aOff;
        const uint32_t akl = sb + (cur ? AK1_L : AK0_L) + (uint32_t)(wm * 16 * PB) + aOff;
        const uint32_t hbh = sb + HB_H + (uint32_t)(wn * 32 * PB) + bOff;
        const uint32_t hbl = sb + HB_L + (uint32_t)(wn * 32 * PB) + bOff;

        // prefetch next k into the other buffer (overlaps the mma below)
        if (k < 3) stage_ak(k + 1, cur ? AK0_H : AK1_H, cur ? AK0_L : AK1_L);

        float Sid[4][4], Sab[4][4];
        #pragma unroll
        for (int nt = 0; nt < 4; nt++)
            #pragma unroll
            for (int q = 0; q < 4; q++) { Sid[nt][q] = 0.f; Sab[nt][q] = 0.f; }

        #pragma unroll
        for (int ks = 0; ks < 8; ks++) {
            uint32_t ah[4], al[4], bh[2][4], bl[2][4];
            ldm_x4(ah, akh + ks * 32);
            ldm_x4(al, akl + ks * 32);
            #pragma unroll
            for (int nh = 0; nh < 2; nh++) {
                ldm_x4(bh[nh], hbh + nh * 16 * PB + ks * 32);
                ldm_x4(bl[nh], hbl + nh * 16 * PB + ks * 32);
            }

            #pragma unroll
            for (int nt = 0; nt < 4; nt++) {
                const uint32_t* bhr = &bh[nt >> 1][(nt & 1) * 2];
                const uint32_t* blr = &bl[nt >> 1][(nt & 1) * 2];
                mma16816(Sid[nt], ah, bhr);
                mma16816(Sid[nt], al, bhr);
                mma16816(Sid[nt], ah, blr);
            }

            uint32_t m01 = sgn_s[((k * 8 + ks) * 4 + t) * 2];
            uint32_t m23 = sgn_s[((k * 8 + ks) * 4 + t) * 2 + 1];
            #pragma unroll
            for (int r = 0; r < 4; r++) {
                uint32_t mm = (r < 2) ? m01 : m23;
                al[r] = al[r] ^ (ah[r] & 0x80008000u) ^ mm;
                ah[r] = (ah[r] & 0x7FFF7FFFu) ^ mm;
            }
            #pragma unroll
            for (int nh = 0; nh < 2; nh++)
                #pragma unroll
                for (int r = 0; r < 4; r++) {
                    bl[nh][r] = bl[nh][r] ^ (bh[nh][r] & 0x80008000u);
                    bh[nh][r] = bh[nh][r] & 0x7FFF7FFFu;
                }

            #pragma unroll
            for (int nt = 0; nt < 4; nt++) {
                const uint32_t* bhr = &bh[nt >> 1][(nt & 1) * 2];
                const uint32_t* blr = &bl[nt >> 1][(nt & 1) * 2];
                mma16816(Sab[nt], ah, bhr);
                mma16816(Sab[nt], al, bhr);
                mma16816(Sab[nt], ah, blr);
            }
        }
        __syncthreads();   // next buffer staged AND this buffer's reads done

        uint32_t mk = (k == 0) ? km0 : (k == 1) ? km1 : (k == 2) ? km2 : km3;
        #pragma unroll
        for (int nt = 0; nt < 4; nt++)
            #pragma unroll
            for (int q = 0; q < 4; q++) {
                float combo = fmaf(0.6f, Sid[nt][q], 0.4f * Sab[nt][q]);
                int p = nt * 4 + q;
                if ((mk >> p) & 1u) alpha[nt][q] = combo;
            }
    }

    // ---- softmax in registers ----
    float mloc[2];
    #pragma unroll
    for (int qh = 0; qh < 2; qh++) {
        float m = NEG_INF_F;
        #pragma unroll
        for (int nt = 0; nt < 4; nt++) {
            m = fmaxf(m, alpha[nt][qh * 2 + 0]);
            m = fmaxf(m, alpha[nt][qh * 2 + 1]);
        }
        m = fmaxf(m, __shfl_xor_sync(0xffffffffu, m, 1));
        m = fmaxf(m, __shfl_xor_sync(0xffffffffu, m, 2));
        mloc[qh] = m;
    }
    if (t == 0) {
        rmax[(wm * 16 + 0 * 8 + g) * 4 + wn] = mloc[0];
        rmax[(wm * 16 + 1 * 8 + g) * 4 + wn] = mloc[1];
    }
    __syncthreads();

    float inv[2];
    #pragma unroll
    for (int qh = 0; qh < 2; qh++) {
        int row = wm * 16 + qh * 8 + g;
        float m = fmaxf(fmaxf(rmax[row * 4 + 0], rmax[row * 4 + 1]),
                        fmaxf(rmax[row * 4 + 2], rmax[row * 4 + 3]));
        float s = 0.f;
        #pragma unroll
        for (int nt = 0; nt < 4; nt++) {
            alpha[nt][qh * 2 + 0] = __expf(alpha[nt][qh * 2 + 0] - m);
            alpha[nt][qh * 2 + 1] = __expf(alpha[nt][qh * 2 + 1] - m);
            s += alpha[nt][qh * 2 + 0] + alpha[nt][qh * 2 + 1];
        }
        s += __shfl_xor_sync(0xffffffffu, s, 1);
        s += __shfl_xor_sync(0xffffffffu, s, 2);
        if (t == 0) rsum[row * 4 + wn] = s;
    }
    __syncthreads();
    #pragma unroll
    for (int qh = 0; qh < 2; qh++) {
        int row = wm * 16 + qh * 8 + g;
        float s = (rsum[row * 4 + 0] + rsum[row * 4 + 1]) +
                  (rsum[row * 4 + 2] + rsum[row * 4 + 3]);
        inv[qh] = 1.f / s;
    }

    // ---- write attn probs as bf16 hi/lo ATT tiles (overlay AK0) ----
    #pragma unroll
    for (int qh = 0; qh < 2; qh++) {
        int row = wm * 16 + qh * 8 + g;
        #pragma unroll
        for (int nt = 0; nt < 4; nt++) {
            float p0 = alpha[nt][qh * 2 + 0] * inv[qh];
            float p1 = alpha[nt][qh * 2 + 1] * inv[qh];
            __nv_bfloat16 h0 = __float2bfloat16(p0);
            __nv_bfloat16 h1 = __float2bfloat16(p1);
            uint32_t hw = pack_bf2(p0, p1);
            uint32_t lw = pack_bf2(p0 - __bfloat162float(h0),
                                   p1 - __bfloat162float(h1));
            uint32_t off = (uint32_t)(row * PB + (wn * 32 + nt * 8 + 2 * t) * 2);
            *(uint32_t*)(smem + ATT_H + off) = hw;
            *(uint32_t*)(smem + ATT_L + off) = lw;
        }
    }
    __syncthreads();

    // ---- AV GEMM: out = attn @ H; B-frags via trans ldmatrix from HB ----
    float O[4][4];
    #pragma unroll
    for (int nt = 0; nt < 4; nt++)
        #pragma unroll
        for (int q = 0; q < 4; q++) O[nt][q] = 0.f;

    const uint32_t ath = sb + ATT_H + (uint32_t)(wm * 16 * PB) + aOff;
    const uint32_t atl = sb + ATT_L + (uint32_t)(wm * 16 * PB) + aOff;

    #pragma unroll
    for (int ks = 0; ks < 8; ks++) {
        uint32_t ah[4], al[4], bh[2][4], bl[2][4];
        ldm_x4(ah, ath + ks * 32);
        ldm_x4(al, atl + ks * 32);
        #pragma unroll
        for (int nh = 0; nh < 2; nh++) {
            uint32_t base = (uint32_t)(ks * 16 * PB + (wn * 32 + nh * 16) * 2) + bOffT;
            ldm_x4_trans(bh[nh], sb + HB_H + base);
            ldm_x4_trans(bl[nh], sb + HB_L + base);
        }
        #pragma unroll
        for (int nt = 0; nt < 4; nt++) {
            const uint32_t* bhr = &bh[nt >> 1][(nt & 1) * 2];
            const uint32_t* blr = &bl[nt >> 1][(nt & 1) * 2];
            mma16816(O[nt], ah, bhr);
            mma16816(O[nt], al, bhr);
            mma16816(O[nt], ah, blr);
        }
    }

    #pragma unroll
    for (int nt = 0; nt < 4; nt++) {
        int row0 = ibase + wm * 16 + g;
        int col  = wn * 32 + nt * 8 + t * 2;
        *(float2*)&out[(size_t)row0 * 128 + col] =
            make_float2(O[nt][0], O[nt][1]);
        *(float2*)&out[(size_t)(row0 + 8) * 128 + col] =
            make_float2(O[nt][2], O[nt][3]);
    }
}

// ============================================================================
// Launch: fork/join — attn_tc beside bconv -> attr_gemm.
// ============================================================================
extern "C" void kernel_launch(void* const* d_in, const int* in_sizes, int n_in,
                              void* d_out, int out_size)
{
    const float* hidden   = (const float*)d_in[0];  // [64,128,128]
    const int*   adj      = (const int*)  d_in[1];  // [64,128,128]
    const float* a        = (const float*)d_in[2];  // [128,4]
    const float* A_attr   = (const float*)d_in[3];  // [64,128,1000]
    const float* attr_emb = (const float*)d_in[4];  // [1000,128]

    float* out       = (float*)d_out;
    float* out_attn  = out;                   // output    [64,128,128]
    float* out_attr  = out + 64 * 128 * 128;  // attr_sess [64,128,128]

    static cudaStream_t s_side = nullptr;
    static cudaEvent_t  ev_fork = nullptr, ev_join = nullptr;
    if (s_side == nullptr) {
        cudaStreamCreateWithFlags(&s_side, cudaStreamNonBlocking);
        cudaEventCreateWithFlags(&ev_fork, cudaEventDisableTiming);
        cudaEventCreateWithFlags(&ev_join, cudaEventDisableTiming);
        cudaFuncSetAttribute(attn_tc_kernel,
                             cudaFuncAttributeMaxDynamicSharedMemorySize,
                             SMEM_ATTN_TC);
        cudaFuncSetAttribute(attr_gemm_mma,
                             cudaFuncAttributeMaxDynamicSharedMemorySize,
                             SMEM_GEMM);
    }

    cudaEventRecord(ev_fork, 0);
    cudaStreamWaitEvent(s_side, ev_fork, 0);

    attn_tc_kernel<<<dim3(64, 4), 256, SMEM_ATTN_TC, s_side>>>(
        hidden, adj, a, out_attn);
    cudaEventRecord(ev_join, s_side);

    bconv_kernel<<<16, 256>>>(attr_emb);
    attr_gemm_mma<<<128, 256, SMEM_GEMM>>>(A_attr, out_attr);

    cudaStreamWaitEvent(0, ev_join, 0);
}